// round 2
// baseline (speedup 1.0000x reference)
#include <cuda_runtime.h>

#define NODES_MAX 100000
#define EDGES_MAX 1000000
#define HEADS 4
#define CDIM 16
#define DIM 64
#define NEG_SLOPE 0.2f

// ---- scratch (static __device__ arrays; no allocation) ----
__device__ float  g_h[NODES_MAX * DIM];          // 25.6 MB, L2-resident
__device__ float  g_asrc[NODES_MAX * HEADS];
__device__ float  g_adst[NODES_MAX * HEADS];
__device__ int    g_counts[NODES_MAX];
__device__ int    g_offsets[NODES_MAX];
__device__ int    g_cursor[NODES_MAX];
__device__ int    g_partials[256];
__device__ float4 g_es[EDGES_MAX];               // per-edge logits (4 heads), CSR order
__device__ int    g_srcs[EDGES_MAX];             // src node id, CSR order
__device__ int    g_is64;                        // edge_index dtype flag

// ---------------------------------------------------------------------------
// Detect whether edge_index is int64 (all odd 32-bit words zero since values
// < 100000) or int32. One warp, ballot over 64 sampled odd words.
__global__ void k_detect(const unsigned* __restrict__ ei, int e) {
    unsigned lane = threadIdx.x;
    unsigned v1 = ei[2u * lane + 1u];
    unsigned v2 = ei[2u * (lane + 32u) + 1u];
    int nz = (v1 != 0u) || (v2 != 0u);
    unsigned any = __ballot_sync(0xffffffffu, nz);
    if (lane == 0) g_is64 = (any == 0u) ? 1 : 0;
}

__device__ __forceinline__ int edge_idx(const void* ei, long long pos, int is64, int n) {
    int v;
    if (is64) v = (int)((const long long*)ei)[pos];
    else      v = ((const int*)ei)[pos];
    // clamp: never trap on a wild address
    v = v < 0 ? 0 : (v >= n ? n - 1 : v);
    return v;
}

__global__ void k_zero(int n) {
    int i = blockIdx.x * blockDim.x + threadIdx.x;
    if (i < n) g_counts[i] = 0;
}

// h = x @ W (64x64), plus per-head attention scalars a_src, a_dst.
// 256 threads/block, 4 threads per row (one head each), W staged in smem.
__global__ void k_gemm(const float* __restrict__ x, const float* __restrict__ W,
                       const float* __restrict__ att_s, const float* __restrict__ att_d,
                       int n) {
    __shared__ float Ws[64 * 64];
    int tid = threadIdx.x;
    for (int i = tid; i < 4096; i += 256) Ws[i] = W[i];
    __syncthreads();

    int row = blockIdx.x * 64 + (tid >> 2);
    int q   = tid & 3;                 // head index handled by this thread
    bool valid = row < n;

    float xr[16];
    if (valid) {
        const float4* xp = (const float4*)(x + row * 64 + q * 16);
        float4 a = xp[0], b = xp[1], c = xp[2], d = xp[3];
        xr[0]=a.x; xr[1]=a.y; xr[2]=a.z; xr[3]=a.w;
        xr[4]=b.x; xr[5]=b.y; xr[6]=b.z; xr[7]=b.w;
        xr[8]=c.x; xr[9]=c.y; xr[10]=c.z; xr[11]=c.w;
        xr[12]=d.x; xr[13]=d.y; xr[14]=d.z; xr[15]=d.w;
    } else {
        #pragma unroll
        for (int i = 0; i < 16; i++) xr[i] = 0.f;
    }

    float acc[16];
    #pragma unroll
    for (int j = 0; j < 16; j++) acc[j] = 0.f;

    int laneBase = (tid & 31) & ~3;    // first lane of this 4-thread group
    #pragma unroll
    for (int k = 0; k < 64; k++) {
        float xk = __shfl_sync(0xffffffffu, xr[k & 15], laneBase + (k >> 4));
        const float* wrow = Ws + k * 64 + q * 16;
        #pragma unroll
        for (int j = 0; j < 16; j++) acc[j] = fmaf(xk, wrow[j], acc[j]);
    }

    if (valid) {
        float4* hp = (float4*)(g_h + row * 64 + q * 16);
        hp[0] = make_float4(acc[0], acc[1], acc[2], acc[3]);
        hp[1] = make_float4(acc[4], acc[5], acc[6], acc[7]);
        hp[2] = make_float4(acc[8], acc[9], acc[10], acc[11]);
        hp[3] = make_float4(acc[12], acc[13], acc[14], acc[15]);
        float as = 0.f, ad = 0.f;
        #pragma unroll
        for (int j = 0; j < 16; j++) {
            as = fmaf(acc[j], __ldg(att_s + q * 16 + j), as);
            ad = fmaf(acc[j], __ldg(att_d + q * 16 + j), ad);
        }
        g_asrc[row * 4 + q] = as;
        g_adst[row * 4 + q] = ad;
    }
}

// histogram of in-degrees
__global__ void k_count(const void* __restrict__ ei, int e, int n) {
    int i = blockIdx.x * blockDim.x + threadIdx.x;
    if (i >= e) return;
    int is64 = g_is64;
    int d = edge_idx(ei, (long long)e + i, is64, n);
    atomicAdd(&g_counts[d], 1);
}

// 3-phase exclusive scan over g_counts -> g_offsets (+ cursor copy)
__global__ void k_scan1(int n) {
    __shared__ int sd[512];
    int idx = blockIdx.x * 512 + threadIdx.x;
    sd[threadIdx.x] = (idx < n) ? g_counts[idx] : 0;
    __syncthreads();
    for (int s = 256; s > 0; s >>= 1) {
        if (threadIdx.x < s) sd[threadIdx.x] += sd[threadIdx.x + s];
        __syncthreads();
    }
    if (threadIdx.x == 0) g_partials[blockIdx.x] = sd[0];
}

__global__ void k_scan2(int nb) {
    __shared__ int sd[256];
    int t = threadIdx.x;
    int own = (t < nb) ? g_partials[t] : 0;
    sd[t] = own;
    __syncthreads();
    for (int d = 1; d < 256; d <<= 1) {
        int v = sd[t];
        if (t >= d) v += sd[t - d];
        __syncthreads();
        sd[t] = v;
        __syncthreads();
    }
    if (t < nb) g_partials[t] = sd[t] - own;   // exclusive
}

__global__ void k_scan3(int n) {
    __shared__ int sd[512];
    int t = threadIdx.x;
    int idx = blockIdx.x * 512 + t;
    int own = (idx < n) ? g_counts[idx] : 0;
    sd[t] = own;
    __syncthreads();
    for (int d = 1; d < 512; d <<= 1) {
        int v = sd[t];
        if (t >= d) v += sd[t - d];
        __syncthreads();
        sd[t] = v;
        __syncthreads();
    }
    int off = g_partials[blockIdx.x] + sd[t] - own;
    if (idx < n) { g_offsets[idx] = off; g_cursor[idx] = off; }
}

// scatter edges into CSR order, computing leaky-relu logits on the fly
__global__ void k_scatter(const void* __restrict__ ei, int e, int n) {
    int i = blockIdx.x * blockDim.x + threadIdx.x;
    if (i >= e) return;
    int is64 = g_is64;
    int s = edge_idx(ei, (long long)i, is64, n);
    int d = edge_idx(ei, (long long)e + i, is64, n);
    int pos = atomicAdd(&g_cursor[d], 1);
    float4 as = *(const float4*)(g_asrc + s * 4);
    float4 ad = *(const float4*)(g_adst + d * 4);
    float4 ev;
    ev.x = as.x + ad.x; ev.x = ev.x >= 0.f ? ev.x : NEG_SLOPE * ev.x;
    ev.y = as.y + ad.y; ev.y = ev.y >= 0.f ? ev.y : NEG_SLOPE * ev.y;
    ev.z = as.z + ad.z; ev.z = ev.z >= 0.f ? ev.z : NEG_SLOPE * ev.z;
    ev.w = as.w + ad.w; ev.w = ev.w >= 0.f ? ev.w : NEG_SLOPE * ev.w;
    g_es[pos]   = ev;
    g_srcs[pos] = s;
}

// warp per node: segment softmax (max, sum) + weighted gather-aggregate of
// h[src], fused bias + LayerNorm. Lane l owns channels {2l, 2l+1}; head = l/8.
__global__ void k_node(const float* __restrict__ bias, const float* __restrict__ gamma,
                       const float* __restrict__ beta, float* __restrict__ out, int n) {
    int warpId = (blockIdx.x * blockDim.x + threadIdx.x) >> 5;
    int lane   = threadIdx.x & 31;
    if (warpId >= n) return;

    int beg = g_offsets[warpId];
    int deg = g_counts[warpId];
    unsigned FULL = 0xffffffffu;

    // phase A1: per-head max over incoming edges
    float m0 = -3.0e38f, m1 = -3.0e38f, m2 = -3.0e38f, m3 = -3.0e38f;
    for (int i = lane; i < deg; i += 32) {
        float4 ev = g_es[beg + i];
        m0 = fmaxf(m0, ev.x); m1 = fmaxf(m1, ev.y);
        m2 = fmaxf(m2, ev.z); m3 = fmaxf(m3, ev.w);
    }
    #pragma unroll
    for (int o = 16; o; o >>= 1) {
        m0 = fmaxf(m0, __shfl_xor_sync(FULL, m0, o));
        m1 = fmaxf(m1, __shfl_xor_sync(FULL, m1, o));
        m2 = fmaxf(m2, __shfl_xor_sync(FULL, m2, o));
        m3 = fmaxf(m3, __shfl_xor_sync(FULL, m3, o));
    }

    // phase A2: per-head exp-sum
    float s0 = 0.f, s1 = 0.f, s2 = 0.f, s3 = 0.f;
    for (int i = lane; i < deg; i += 32) {
        float4 ev = g_es[beg + i];
        s0 += __expf(ev.x - m0); s1 += __expf(ev.y - m1);
        s2 += __expf(ev.z - m2); s3 += __expf(ev.w - m3);
    }
    #pragma unroll
    for (int o = 16; o; o >>= 1) {
        s0 += __shfl_xor_sync(FULL, s0, o);
        s1 += __shfl_xor_sync(FULL, s1, o);
        s2 += __shfl_xor_sync(FULL, s2, o);
        s3 += __shfl_xor_sync(FULL, s3, o);
    }
    float i0 = 1.f / (s0 + 1e-16f), i1 = 1.f / (s1 + 1e-16f);
    float i2 = 1.f / (s2 + 1e-16f), i3 = 1.f / (s3 + 1e-16f);

    int hd = lane >> 3;
    float accx = 0.f, accy = 0.f;

    // phase B: serial over edges, coalesced 256B gather of h[src] per edge
    for (int base = 0; base < deg; base += 32) {
        int i = base + lane;
        float a0 = 0.f, a1 = 0.f, a2 = 0.f, a3 = 0.f;
        int sv = 0;
        if (i < deg) {
            float4 ev = g_es[beg + i];
            sv = g_srcs[beg + i];
            a0 = __expf(ev.x - m0) * i0;
            a1 = __expf(ev.y - m1) * i1;
            a2 = __expf(ev.z - m2) * i2;
            a3 = __expf(ev.w - m3) * i3;
        }
        int cnt = min(32, deg - base);
        for (int j = 0; j < cnt; j++) {
            float A0 = __shfl_sync(FULL, a0, j);
            float A1 = __shfl_sync(FULL, a1, j);
            float A2 = __shfl_sync(FULL, a2, j);
            float A3 = __shfl_sync(FULL, a3, j);
            int   ss = __shfl_sync(FULL, sv, j);
            float al = (hd == 0) ? A0 : (hd == 1) ? A1 : (hd == 2) ? A2 : A3;
            float2 hv = *(const float2*)(g_h + ss * 64 + lane * 2);
            accx = fmaf(al, hv.x, accx);
            accy = fmaf(al, hv.y, accy);
        }
    }

    // bias + LayerNorm over the 64 channels of this node (2 per lane)
    float o0 = accx + __ldg(bias + lane * 2);
    float o1 = accy + __ldg(bias + lane * 2 + 1);
    float ssum = o0 + o1;
    float ssq  = o0 * o0 + o1 * o1;
    #pragma unroll
    for (int o = 16; o; o >>= 1) {
        ssum += __shfl_xor_sync(FULL, ssum, o);
        ssq  += __shfl_xor_sync(FULL, ssq, o);
    }
    float mu  = ssum * (1.f / 64.f);
    float var = ssq * (1.f / 64.f) - mu * mu;
    float r   = rsqrtf(var + 1e-5f);
    float2 res;
    res.x = (o0 - mu) * r * __ldg(gamma + lane * 2)     + __ldg(beta + lane * 2);
    res.y = (o1 - mu) * r * __ldg(gamma + lane * 2 + 1) + __ldg(beta + lane * 2 + 1);
    *(float2*)(out + warpId * 64 + lane * 2) = res;
}

// ---------------------------------------------------------------------------
extern "C" void kernel_launch(void* const* d_in, const int* in_sizes, int n_in,
                              void* d_out, int out_size) {
    const float* x     = (const float*)d_in[0];
    const void*  ei    = d_in[1];
    const float* W     = (const float*)d_in[2];
    const float* att_s = (const float*)d_in[3];
    const float* att_d = (const float*)d_in[4];
    const float* bias  = (const float*)d_in[5];
    const float* gamma = (const float*)d_in[6];
    const float* beta  = (const float*)d_in[7];
    float* out = (float*)d_out;

    int n = in_sizes[0] / DIM;   // 100000
    int e = in_sizes[1] / 2;     // 1000000
    int nb = (n + 511) / 512;    // 196 scan blocks (<=256)

    k_detect<<<1, 32>>>((const unsigned*)ei, e);
    k_zero<<<(n + 255) / 256, 256>>>(n);
    k_gemm<<<(n + 63) / 64, 256>>>(x, W, att_s, att_d, n);
    k_count<<<(e + 255) / 256, 256>>>(ei, e, n);
    k_scan1<<<nb, 512>>>(n);
    k_scan2<<<1, 256>>>(nb);
    k_scan3<<<nb, 512>>>(n);
    k_scatter<<<(e + 255) / 256, 256>>>(ei, e, n);
    k_node<<<(n + 7) / 8, 256>>>(bias, gamma, beta, out, n);
}

// round 3
// speedup vs baseline: 1.9785x; 1.9785x over previous
#include <cuda_runtime.h>

#define HEADS 4
#define DIM 64
#define NEG_SLOPE 0.2f
#define NODES_MAX 100000
#define EDGES_MAX 1000000

// ---- scratch (static __device__; no allocation) ----
__device__ float  g_h[NODES_MAX * DIM];      // 25.6 MB, L2-resident
__device__ float4 g_asrc[NODES_MAX];         // per-node src attention (4 heads)
__device__ float4 g_adst[NODES_MAX];         // per-node dst attention (4 heads)
__device__ int    g_counts[NODES_MAX];
__device__ int    g_offsets[NODES_MAX];
__device__ int    g_cursor[NODES_MAX];
__device__ int    g_partials[256];
__device__ int    g_srcs[EDGES_MAX];         // src node id in CSR-by-dst order
__device__ int    g_is64;

// packed f32x2 FMA (ptxas won't auto-fuse; sm_103a FFMA2)
__device__ __forceinline__ void ffma2(unsigned long long& d, unsigned long long a,
                                      unsigned long long b) {
    asm("fma.rn.f32x2 %0, %1, %2, %0;" : "+l"(d) : "l"(a), "l"(b));
}

// ---------------------------------------------------------------------------
// zero counts + detect edge_index dtype (block 0 / warp 0 does detection)
__global__ void k_zero_detect(const unsigned* __restrict__ ei, int n) {
    int i = blockIdx.x * blockDim.x + threadIdx.x;
    if (i < n) g_counts[i] = 0;
    if (blockIdx.x == 0 && threadIdx.x < 32) {
        unsigned lane = threadIdx.x;
        unsigned v1 = ei[2u * lane + 1u];
        unsigned v2 = ei[2u * (lane + 32u) + 1u];
        int nz = (v1 != 0u) || (v2 != 0u);
        unsigned any = __ballot_sync(0xffffffffu, nz);
        if (lane == 0) g_is64 = (any == 0u) ? 1 : 0;
    }
}

__device__ __forceinline__ int edge_idx(const void* ei, long long pos, int is64, int n) {
    int v;
    if (is64) v = (int)((const long long*)ei)[pos];
    else      v = ((const int*)ei)[pos];
    v = v < 0 ? 0 : (v >= n ? n - 1 : v);   // never trap on wild address
    return v;
}

// ---------------------------------------------------------------------------
// h = x @ W + attention scalars. Warp = 32 rows; lane owns W columns {2l,2l+1}
// in 128 registers; x staged in smem as duplicated (v,v) pairs so the k-loop
// is 1 broadcast LDS.64 + 1 FFMA2 per row per k. 4 rows in flight for ILP.
__global__ void __launch_bounds__(256) k_gemm(
        const float* __restrict__ x, const float* __restrict__ W,
        const float* __restrict__ att_s, const float* __restrict__ att_d, int n) {
    __shared__ unsigned long long sx[8][4 * 64];   // per warp: 4 rows x 64 dup pairs
    int tid = threadIdx.x, lane = tid & 31, wid = tid >> 5;
    int rowBase = (blockIdx.x * 8 + wid) * 32;

    unsigned long long Wr[64];
    #pragma unroll
    for (int k = 0; k < 64; k++)
        Wr[k] = *(const unsigned long long*)(W + k * 64 + lane * 2);
    float2 asw = *(const float2*)(att_s + lane * 2);
    float2 adw = *(const float2*)(att_d + lane * 2);

    unsigned FULL = 0xffffffffu;
    int hdsel = lane >> 3;      // head for columns 2l,2l+1

    for (int r4 = 0; r4 < 32; r4 += 4) {
        int row0 = rowBase + r4;

        // stage 4 rows (256 floats) as duplicated pairs
        #pragma unroll
        for (int it = 0; it < 4; it++) {
            int g2 = it * 32 + lane;                // float2 index in 4-row span
            int r = g2 >> 5;                        // local row (64 floats = 32 float2)
            float2 v = make_float2(0.f, 0.f);
            if (row0 + r < n) v = ((const float2*)x)[(long long)row0 * 32 + g2];
            sx[wid][g2 * 2]     = ((unsigned long long)__float_as_uint(v.x) << 32) |
                                   (unsigned long long)__float_as_uint(v.x);
            sx[wid][g2 * 2 + 1] = ((unsigned long long)__float_as_uint(v.y) << 32) |
                                   (unsigned long long)__float_as_uint(v.y);
        }
        __syncwarp();

        unsigned long long a0 = 0ull, a1 = 0ull, a2 = 0ull, a3 = 0ull;
        const unsigned long long* xr = &sx[wid][0];
        #pragma unroll
        for (int k = 0; k < 64; k++) {
            ffma2(a0, xr[k],       Wr[k]);
            ffma2(a1, xr[64 + k],  Wr[k]);
            ffma2(a2, xr[128 + k], Wr[k]);
            ffma2(a3, xr[192 + k], Wr[k]);
        }
        __syncwarp();

        unsigned long long accs[4] = {a0, a1, a2, a3};
        #pragma unroll
        for (int r = 0; r < 4; r++) {
            int row = row0 + r;
            float c0 = __uint_as_float((unsigned)(accs[r] & 0xffffffffull));
            float c1 = __uint_as_float((unsigned)(accs[r] >> 32));
            if (row < n) {
                *(float2*)(g_h + (long long)row * 64 + lane * 2) = make_float2(c0, c1);
            }
            float ts = c0 * asw.x + c1 * asw.y;
            float td = c0 * adw.x + c1 * adw.y;
            #pragma unroll
            for (int m = 1; m < 8; m <<= 1) {
                ts += __shfl_xor_sync(FULL, ts, m);
                td += __shfl_xor_sync(FULL, td, m);
            }
            if (row < n && (lane & 7) == 0) {
                ((float*)g_asrc)[row * 4 + hdsel] = ts;
                ((float*)g_adst)[row * 4 + hdsel] = td;
            }
        }
    }
}

// ---------------------------------------------------------------------------
__global__ void k_count(const void* __restrict__ ei, int e, int n) {
    int i = blockIdx.x * blockDim.x + threadIdx.x;
    if (i >= e) return;
    int d = edge_idx(ei, (long long)e + i, g_is64, n);
    atomicAdd(&g_counts[d], 1);
}

__global__ void k_scan1(int n) {
    __shared__ int sd[512];
    int idx = blockIdx.x * 512 + threadIdx.x;
    sd[threadIdx.x] = (idx < n) ? g_counts[idx] : 0;
    __syncthreads();
    for (int s = 256; s > 0; s >>= 1) {
        if (threadIdx.x < s) sd[threadIdx.x] += sd[threadIdx.x + s];
        __syncthreads();
    }
    if (threadIdx.x == 0) g_partials[blockIdx.x] = sd[0];
}

__global__ void k_scan2(int nb) {
    __shared__ int sd[256];
    int t = threadIdx.x;
    int own = (t < nb) ? g_partials[t] : 0;
    sd[t] = own;
    __syncthreads();
    for (int d = 1; d < 256; d <<= 1) {
        int v = sd[t];
        if (t >= d) v += sd[t - d];
        __syncthreads();
        sd[t] = v;
        __syncthreads();
    }
    if (t < nb) g_partials[t] = sd[t] - own;
}

__global__ void k_scan3(int n) {
    __shared__ int sd[512];
    int t = threadIdx.x;
    int idx = blockIdx.x * 512 + t;
    int own = (idx < n) ? g_counts[idx] : 0;
    sd[t] = own;
    __syncthreads();
    for (int d = 1; d < 512; d <<= 1) {
        int v = sd[t];
        if (t >= d) v += sd[t - d];
        __syncthreads();
        sd[t] = v;
        __syncthreads();
    }
    int off = g_partials[blockIdx.x] + sd[t] - own;
    if (idx < n) { g_offsets[idx] = off; g_cursor[idx] = off; }
}

// scatter only src ids into CSR-by-dst order
__global__ void k_scatter(const void* __restrict__ ei, int e, int n) {
    int i = blockIdx.x * blockDim.x + threadIdx.x;
    if (i >= e) return;
    int is64 = g_is64;
    int s = edge_idx(ei, (long long)i, is64, n);
    int d = edge_idx(ei, (long long)e + i, is64, n);
    int pos = atomicAdd(&g_cursor[d], 1);
    g_srcs[pos] = s;
}

// ---------------------------------------------------------------------------
// warp per node, SINGLE pass: unnormalized softmax accumulation.
// lane owns channels {2l,2l+1}; head = lane>>3. Per-chunk alphas via smem.
__global__ void __launch_bounds__(256) k_node(
        const float* __restrict__ bias, const float* __restrict__ gamma,
        const float* __restrict__ beta, float* __restrict__ out, int n) {
    __shared__ float4 s_ex[8][32];
    __shared__ int    s_src[8][32];
    int wslot = threadIdx.x >> 5, lane = threadIdx.x & 31;
    int node = blockIdx.x * 8 + wslot;
    if (node >= n) return;
    unsigned FULL = 0xffffffffu;

    int beg = g_offsets[node];
    int deg = g_counts[node];
    float4 ad = g_adst[node];
    int hd = lane >> 3;

    float s0 = 0.f, s1 = 0.f, s2 = 0.f, s3 = 0.f;
    float accx = 0.f, accy = 0.f;
    const float* hb = g_h + lane * 2;

    for (int base = 0; base < deg; base += 32) {
        int i = base + lane;
        float4 ex4 = make_float4(0.f, 0.f, 0.f, 0.f);
        int sv = 0;
        if (i < deg) {
            sv = g_srcs[beg + i];
            float4 as = g_asrc[sv];
            float e0 = as.x + ad.x; e0 = e0 >= 0.f ? e0 : NEG_SLOPE * e0;
            float e1 = as.y + ad.y; e1 = e1 >= 0.f ? e1 : NEG_SLOPE * e1;
            float e2 = as.z + ad.z; e2 = e2 >= 0.f ? e2 : NEG_SLOPE * e2;
            float e3 = as.w + ad.w; e3 = e3 >= 0.f ? e3 : NEG_SLOPE * e3;
            ex4.x = __expf(e0); ex4.y = __expf(e1);
            ex4.z = __expf(e2); ex4.w = __expf(e3);
            s0 += ex4.x; s1 += ex4.y; s2 += ex4.z; s3 += ex4.w;
        }
        s_ex[wslot][lane] = ex4;
        s_src[wslot][lane] = sv;
        __syncwarp();
        int cnt = min(32, deg - base);
        for (int j = 0; j < cnt; j++) {
            int   ss = s_src[wslot][j];
            float al = ((const float*)&s_ex[wslot][j])[hd];
            float2 hv = *(const float2*)(hb + (long long)ss * 64);
            accx = fmaf(al, hv.x, accx);
            accy = fmaf(al, hv.y, accy);
        }
        __syncwarp();
    }

    // reduce per-head exp-sums across the warp
    #pragma unroll
    for (int o = 16; o; o >>= 1) {
        s0 += __shfl_xor_sync(FULL, s0, o);
        s1 += __shfl_xor_sync(FULL, s1, o);
        s2 += __shfl_xor_sync(FULL, s2, o);
        s3 += __shfl_xor_sync(FULL, s3, o);
    }
    float s   = (hd == 0) ? s0 : (hd == 1) ? s1 : (hd == 2) ? s2 : s3;
    float inv = 1.f / (s + 1e-16f);

    // bias + LayerNorm over 64 channels (2 per lane)
    float o0 = accx * inv + __ldg(bias + lane * 2);
    float o1 = accy * inv + __ldg(bias + lane * 2 + 1);
    float ssum = o0 + o1;
    float ssq  = o0 * o0 + o1 * o1;
    #pragma unroll
    for (int o = 16; o; o >>= 1) {
        ssum += __shfl_xor_sync(FULL, ssum, o);
        ssq  += __shfl_xor_sync(FULL, ssq, o);
    }
    float mu  = ssum * (1.f / 64.f);
    float var = ssq * (1.f / 64.f) - mu * mu;
    float r   = rsqrtf(var + 1e-5f);
    float2 res;
    res.x = (o0 - mu) * r * __ldg(gamma + lane * 2)     + __ldg(beta + lane * 2);
    res.y = (o1 - mu) * r * __ldg(gamma + lane * 2 + 1) + __ldg(beta + lane * 2 + 1);
    *(float2*)(out + (long long)node * 64 + lane * 2) = res;
}

// ---------------------------------------------------------------------------
extern "C" void kernel_launch(void* const* d_in, const int* in_sizes, int n_in,
                              void* d_out, int out_size) {
    const float* x     = (const float*)d_in[0];
    const void*  ei    = d_in[1];
    const float* W     = (const float*)d_in[2];
    const float* att_s = (const float*)d_in[3];
    const float* att_d = (const float*)d_in[4];
    const float* bias  = (const float*)d_in[5];
    const float* gamma = (const float*)d_in[6];
    const float* beta  = (const float*)d_in[7];
    float* out = (float*)d_out;

    int n = in_sizes[0] / DIM;   // 100000
    int e = in_sizes[1] / 2;     // 1000000
    int nb = (n + 511) / 512;    // 196 scan blocks

    k_zero_detect<<<(n + 255) / 256, 256>>>((const unsigned*)ei, n);
    k_gemm<<<(n + 255) / 256, 256>>>(x, W, att_s, att_d, n);
    k_count<<<(e + 255) / 256, 256>>>(ei, e, n);
    k_scan1<<<nb, 512>>>(n);
    k_scan2<<<1, 256>>>(nb);
    k_scan3<<<nb, 512>>>(n);
    k_scatter<<<(e + 255) / 256, 256>>>(ei, e, n);
    k_node<<<(n + 7) / 8, 256>>>(bias, gamma, beta, out, n);
}